// round 16
// baseline (speedup 1.0000x reference)
#include <cuda_runtime.h>
#include <math.h>

// Problem constants
#define N_ROWS 32768
#define DIM    512
#define NSTAGES 8
#define NCODES 4096

// Tile config
#define BM 64          // rows per block
#define BN 128         // codewords per chunk
#define BKC 64         // k-slab per double-buffer stage
// dynamic smem: A [DIM][BM] + 2 x B [BKC][BN]
#define SMEM_FLOATS (DIM*BM + 2*BKC*BN)
#define SMEM_BYTES  (SMEM_FLOATS * 4)

typedef unsigned long long u64;

__device__ float g_res[(size_t)N_ROWS * DIM];            // residual carry
__device__ float g_cbn[(size_t)NSTAGES * NCODES * DIM];  // normalized codebooks

// packed helpers ------------------------------------------------------------
__device__ __forceinline__ u64 dup2(float a) {
    u64 r; asm("mov.b64 %0, {%1, %1};" : "=l"(r) : "f"(a)); return r;
}
// two independent IEEE-RN fp32 FMAs (bit-identical to scalar FFMA per lane)
__device__ __forceinline__ void ffma2(u64& acc, u64 a2, u64 b2) {
    asm("fma.rn.f32x2 %0, %1, %2, %0;" : "+l"(acc) : "l"(a2), "l"(b2));
}
__device__ __forceinline__ void unpack2(u64 v, float& lo, float& hi) {
    asm("mov.b64 {%0, %1}, %2;" : "=f"(lo), "=f"(hi) : "l"(v));
}

// ---------------------------------------------------------------------------
// Normalize codebooks exactly as XLA:CPU does (strict IEEE, no fast-math):
//   S = sum_{k ascending} fadd(S, fmul(c_k, c_k))   (scalar sequential, NO fma)
//   n = max(sqrt_rn(S), 1e-12);  b_k = fdiv_rn(c_k, n)
// ---------------------------------------------------------------------------
__global__ void normalize_cb_kernel(const float* __restrict__ cb) {
    int cw = blockIdx.x * blockDim.x + threadIdx.x;
    if (cw >= NSTAGES * NCODES) return;
    const float* row = cb + (size_t)cw * DIM;
    float* orow = g_cbn + (size_t)cw * DIM;

    float S = 0.0f;
#pragma unroll 8
    for (int k = 0; k < DIM; k++) {
        float v = row[k];
        S = __fadd_rn(S, __fmul_rn(v, v));
    }
    float n = fmaxf(__fsqrt_rn(S), 1e-12f);
#pragma unroll 8
    for (int k = 0; k < DIM; k++) {
        orow[k] = __fdiv_rn(row[k], n);
    }
}

// ---------------------------------------------------------------------------
__global__ void init_kernel(const float* __restrict__ x, float* __restrict__ hard) {
    int i = blockIdx.x * blockDim.x + threadIdx.x;
    int stride = gridDim.x * blockDim.x;
    for (; i < N_ROWS * DIM; i += stride) {
        g_res[i] = x[i];
        hard[i] = 0.0f;
    }
}

// ---------------------------------------------------------------------------
// One RVQ stage. Block = 256 threads, BM=64 rows, full-K residual in SMEM.
// Phase B: 4x8 thread tile, packed f32x2 FMA (2 MACs/inst), B double-buffered.
// Per-accumulator chain remains single-FMA, strictly ascending k -> bit-exact.
// ---------------------------------------------------------------------------
__global__ void __launch_bounds__(256, 1)
stage_kernel(const float* __restrict__ cb,      // original codebook [NCODES][DIM]
             const float* __restrict__ cbn,     // normalized codebook [NCODES][DIM]
             float* __restrict__ hard,          // [N_ROWS][DIM]
             float* __restrict__ ids_out,       // [N_ROWS][NSTAGES] as float, may be null
             int stage) {
    extern __shared__ float smem[];
    float* A_s = smem;                  // [k*BM + row], k in [0,512)
    float* B_s = smem + DIM * BM;       // 2 x [k*BN + cw], k in [0,64)
    __shared__ int   winner[BM];
    __shared__ float rnorm[BM];

    const int t = threadIdx.x;
    const int tx = t & 15;              // 16 -> 8 codewords each (BN=128)
    const int ty = t >> 4;              // 16 -> 4 rows each (BM=64)
    const int rowBase = blockIdx.x * BM;
    const int row = t & 63;
    const int ks = t >> 6;              // 4 K-slices of 128

    // ---- Phase A1: residual tile, transposed ----
    {
        const float4* rr = (const float4*)(g_res + (size_t)(rowBase + row) * DIM);
#pragma unroll 4
        for (int j = 0; j < 32; j++) {
            int k = ks * 128 + j * 4;
            float4 rv = rr[k >> 2];
            A_s[(k + 0) * BM + row] = rv.x;
            A_s[(k + 1) * BM + row] = rv.y;
            A_s[(k + 2) * BM + row] = rv.z;
            A_s[(k + 3) * BM + row] = rv.w;
        }
    }
    __syncthreads();

    // ---- Phase A2: strict sequential row norm (threads 0..63, one per row) ----
    if (t < BM) {
        float S = 0.0f;
#pragma unroll 8
        for (int k = 0; k < DIM; k++) {
            float v = A_s[k * BM + t];
            S = __fadd_rn(S, __fmul_rn(v, v));
        }
        rnorm[t] = fmaxf(__fsqrt_rn(S), 1e-12f);
    }
    __syncthreads();

    // ---- Phase A3: a = res / n, IEEE divide ----
    {
        float n = rnorm[row];
#pragma unroll 4
        for (int j = 0; j < 32; j++) {
            int k = ks * 128 + j * 4;
            A_s[(k + 0) * BM + row] = __fdiv_rn(A_s[(k + 0) * BM + row], n);
            A_s[(k + 1) * BM + row] = __fdiv_rn(A_s[(k + 1) * BM + row], n);
            A_s[(k + 2) * BM + row] = __fdiv_rn(A_s[(k + 2) * BM + row], n);
            A_s[(k + 3) * BM + row] = __fdiv_rn(A_s[(k + 3) * BM + row], n);
        }
    }
    __syncthreads();

    float bestS[4];
    int   bestI[4];
#pragma unroll
    for (int i = 0; i < 4; i++) { bestS[i] = -1e30f; bestI[i] = 0; }

    // B gmem->smem mapping: thread owns codeword cwq, half-slab kq
    const int cwq = t & 127;            // 0..127
    const int kq  = t >> 7;             // 0..1 (k offset kq*32 within slab)

    // ---- Phase B: stream codeword chunks of BN=128 ----
    for (int cwb = 0; cwb < NCODES; cwb += BN) {
        u64 acc[4][4];                  // [row i][cw pair jp] packed f32x2
#pragma unroll
        for (int i = 0; i < 4; i++)
#pragma unroll
            for (int jp = 0; jp < 4; jp++) acc[i][jp] = 0ull;

        const float4* crow4 = (const float4*)(cbn + (size_t)(cwb + cwq) * DIM) + kq * 8;
        float4 pf[8];

        // preload slab 0 and stage it
#pragma unroll
        for (int j = 0; j < 8; j++) pf[j] = crow4[j];
        {
            float* Bd = B_s;            // buffer 0
#pragma unroll
            for (int j = 0; j < 8; j++) {
                int kk = kq * 32 + j * 4;
                Bd[(kk + 0) * BN + cwq] = pf[j].x;
                Bd[(kk + 1) * BN + cwq] = pf[j].y;
                Bd[(kk + 2) * BN + cwq] = pf[j].z;
                Bd[(kk + 3) * BN + cwq] = pf[j].w;
            }
        }

        for (int s = 0; s < DIM / BKC; s++) {
            __syncthreads();            // buf[s&1] ready; all prior FMA done

            if (s < DIM / BKC - 1) {
#pragma unroll
                for (int j = 0; j < 8; j++) pf[j] = crow4[(s + 1) * 16 + j];
            }

            // FFMA2 over this k-slab
            const float* Ab = A_s + (s * BKC) * BM + ty * 4;
            const float* Bb = B_s + (s & 1) * (BKC * BN) + tx * 8;
#pragma unroll 8
            for (int k = 0; k < BKC; k++) {
                float4 a = *(const float4*)(Ab + k * BM);
                ulonglong2 bA = *(const ulonglong2*)(Bb + k * BN);      // (b0,b1),(b2,b3)
                ulonglong2 bB = *(const ulonglong2*)(Bb + k * BN + 4);  // (b4,b5),(b6,b7)
                u64 d0 = dup2(a.x), d1 = dup2(a.y), d2 = dup2(a.z), d3 = dup2(a.w);
                ffma2(acc[0][0], d0, bA.x); ffma2(acc[0][1], d0, bA.y);
                ffma2(acc[0][2], d0, bB.x); ffma2(acc[0][3], d0, bB.y);
                ffma2(acc[1][0], d1, bA.x); ffma2(acc[1][1], d1, bA.y);
                ffma2(acc[1][2], d1, bB.x); ffma2(acc[1][3], d1, bB.y);
                ffma2(acc[2][0], d2, bA.x); ffma2(acc[2][1], d2, bA.y);
                ffma2(acc[2][2], d2, bB.x); ffma2(acc[2][3], d2, bB.y);
                ffma2(acc[3][0], d3, bA.x); ffma2(acc[3][1], d3, bA.y);
                ffma2(acc[3][2], d3, bB.x); ffma2(acc[3][3], d3, bB.y);
            }

            if (s < DIM / BKC - 1) {
                float* Bd = B_s + ((s + 1) & 1) * (BKC * BN);
#pragma unroll
                for (int j = 0; j < 8; j++) {
                    int kk = kq * 32 + j * 4;
                    Bd[(kk + 0) * BN + cwq] = pf[j].x;
                    Bd[(kk + 1) * BN + cwq] = pf[j].y;
                    Bd[(kk + 2) * BN + cwq] = pf[j].z;
                    Bd[(kk + 3) * BN + cwq] = pf[j].w;
                }
            }
        }

        // fused argmax (ascending cw per thread; strict > keeps first index)
#pragma unroll
        for (int jp = 0; jp < 4; jp++) {
            int cw0 = cwb + tx * 8 + jp * 2;
#pragma unroll
            for (int i = 0; i < 4; i++) {
                float v0, v1;
                unpack2(acc[i][jp], v0, v1);
                if (v0 > bestS[i]) { bestS[i] = v0; bestI[i] = cw0; }
                if (v1 > bestS[i]) { bestS[i] = v1; bestI[i] = cw0 + 1; }
            }
        }
    }

    // ---- Phase C: cross-thread argmax reduction (reuse B_s) ----
    __syncthreads();
    float* redS = B_s;                       // [row*16 + tx]
    int*   redI = (int*)(B_s + BM * 16);     // [row*16 + tx]
#pragma unroll
    for (int i = 0; i < 4; i++) {
        redS[(ty * 4 + i) * 16 + tx] = bestS[i];
        redI[(ty * 4 + i) * 16 + tx] = bestI[i];
    }
    __syncthreads();
    if (t < BM) {
        float bs = redS[t * 16];
        int   bi = redI[t * 16];
#pragma unroll
        for (int j = 1; j < 16; j++) {
            float s2 = redS[t * 16 + j];
            int   i2 = redI[t * 16 + j];
            if (s2 > bs || (s2 == bs && i2 < bi)) { bs = s2; bi = i2; }
        }
        winner[t] = bi;
        if (ids_out)
            ids_out[(size_t)(rowBase + t) * NSTAGES + stage] = (float)bi;
    }
    __syncthreads();

    // ---- Phase D: res -= cb[winner]; hard += cb[winner] (elementwise) ----
    {
        int id = winner[row];
        const float4* q = (const float4*)(cb + (size_t)id * DIM);
        float4* hr = (float4*)(hard + (size_t)(rowBase + row) * DIM);
        float4* rr = (float4*)(g_res + (size_t)(rowBase + row) * DIM);
#pragma unroll 4
        for (int j = 0; j < 32; j++) {
            int k4 = ks * 32 + j;
            float4 qq = q[k4];
            float4 h = hr[k4];
            float4 r = rr[k4];
            h.x += qq.x; h.y += qq.y; h.z += qq.z; h.w += qq.w;
            r.x -= qq.x; r.y -= qq.y; r.z -= qq.z; r.w -= qq.w;
            hr[k4] = h;
            rr[k4] = r;
        }
    }
}

// ---------------------------------------------------------------------------
extern "C" void kernel_launch(void* const* d_in, const int* in_sizes, int n_in,
                              void* d_out, int out_size) {
    const float* x  = (const float*)d_in[0];        // [32768, 512]
    const float* cb = (const float*)d_in[1];        // [8, 4096, 512]
    float* out  = (float*)d_out;
    float* hard = out;                              // [32768, 512]
    float* ids  = nullptr;                          // [32768, 8] as float
    if (out_size >= N_ROWS * DIM + N_ROWS * NSTAGES)
        ids = out + (size_t)N_ROWS * DIM;

    cudaFuncSetAttribute(stage_kernel,
                         cudaFuncAttributeMaxDynamicSharedMemorySize, SMEM_BYTES);

    float* cbn_ptr = nullptr;
    cudaGetSymbolAddress((void**)&cbn_ptr, g_cbn);

    // normalize all codebooks (one thread per codeword, strict sequential)
    normalize_cb_kernel<<<(NSTAGES * NCODES + 255) / 256, 256>>>(cb);
    // res = x, hard = 0
    init_kernel<<<2048, 256>>>(x, hard);

    for (int s = 0; s < NSTAGES; s++) {
        stage_kernel<<<N_ROWS / BM, 256, SMEM_BYTES>>>(
            cb + (size_t)s * NCODES * DIM,
            cbn_ptr + (size_t)s * NCODES * DIM,
            hard, ids, s);
    }
}